// round 10
// baseline (speedup 1.0000x reference)
#include <cuda_runtime.h>
#include <cuda_fp16.h>
#include <cstdint>

#define T_SEQ 2048
#define BATCH 2
#define EMBED 512
#define NHEADS 8
#define HD 64
#define FFN_DIM 2048
#define NROWS (T_SEQ * BATCH)      // 4096
#define BH (BATCH * NHEADS)        // 16
#define QKV_LD (3 * EMBED)         // 1536
#define ROWSTRIDE (BATCH * QKV_LD) // 3072
#define S32 40
#define SQ 72                      // stride (elems) for 64-col fp16 tiles

// weight-plane segment offsets (elems) -- hi plane only
#define S_SQKV 0
#define S_SWO  3145728
#define S_CQKV 4194304
#define S_CWO  7340032
#define S_FC1  8388608
#define S_FC2  12582912
#define W_TOT  16777216

// fused-attn smem: Q hi/lo [0,36864); 3 stages of (K-hi + V-hi) (36864 each)
#define FA_QB 36864
#define FA_VOFF 18432
#define FA_SSTG 36864
#define FA_SMEM (FA_QB + 3 * FA_SSTG)  // 147456

// ---------------- device scratch ----------------
__device__ __align__(16) float g_x[NROWS * EMBED];
__device__ __align__(16) float g_y[NROWS * EMBED];
__device__ __align__(16) __half g_xh[NROWS * EMBED], g_xl[NROWS * EMBED];
__device__ __align__(16) __half g_ench[NROWS * EMBED], g_encl[NROWS * EMBED];
__device__ __align__(16) __half g_qkvh[NROWS * QKV_LD], g_qkvl[NROWS * QKV_LD];
__device__ __align__(16) __half g_hidh[NROWS * FFN_DIM], g_hidl[NROWS * FFN_DIM];
__device__ __align__(16) __half g_ah[NROWS * EMBED], g_al[NROWS * EMBED];
__device__ __align__(16) __half g_wbh[W_TOT];
__device__ float g_vsum[BATCH * EMBED];
__device__ float g_vs2[BATCH * EMBED];
__device__ unsigned g_minmax[2];

__device__ __forceinline__ unsigned fenc(float f) {
    unsigned u = __float_as_uint(f);
    return (u & 0x80000000u) ? ~u : (u | 0x80000000u);
}
__device__ __forceinline__ float fdec(unsigned e) {
    return __uint_as_float((e & 0x80000000u) ? (e ^ 0x80000000u) : ~e);
}
__device__ __forceinline__ uint32_t smem_u32(const void* p) {
    uint32_t a;
    asm("{ .reg .u64 t; cvta.to.shared.u64 t, %1; cvt.u32.u64 %0, t; }" : "=r"(a) : "l"(p));
    return a;
}
__device__ __forceinline__ void cpa16(uint32_t d, const void* s) {
    asm volatile("cp.async.cg.shared.global [%0], [%1], 16;" :: "r"(d), "l"(s));
}
#define CPA_COMMIT() asm volatile("cp.async.commit_group;" ::: "memory")
#define CPA_WAIT0()  asm volatile("cp.async.wait_group 0;" ::: "memory")
#define CPA_WAIT1()  asm volatile("cp.async.wait_group 1;" ::: "memory")

__device__ __forceinline__ void ldmx4(uint32_t* r, uint32_t addr) {
    asm volatile("ldmatrix.sync.aligned.m8n8.x4.shared.b16 {%0,%1,%2,%3}, [%4];"
        : "=r"(r[0]), "=r"(r[1]), "=r"(r[2]), "=r"(r[3]) : "r"(addr));
}
__device__ __forceinline__ void ldmx4t(uint32_t* r, uint32_t addr) {
    asm volatile("ldmatrix.sync.aligned.m8n8.x4.trans.shared.b16 {%0,%1,%2,%3}, [%4];"
        : "=r"(r[0]), "=r"(r[1]), "=r"(r[2]), "=r"(r[3]) : "r"(addr));
}
__device__ __forceinline__ void mma16816(float* c, const uint32_t* a, const uint32_t* b) {
    asm volatile("mma.sync.aligned.m16n8k16.row.col.f32.f16.f16.f32 "
        "{%0,%1,%2,%3}, {%4,%5,%6,%7}, {%8,%9}, {%0,%1,%2,%3};"
        : "+f"(c[0]), "+f"(c[1]), "+f"(c[2]), "+f"(c[3])
        : "r"(a[0]), "r"(a[1]), "r"(a[2]), "r"(a[3]), "r"(b[0]), "r"(b[1]));
}
__device__ __forceinline__ void cvt4(float4 v, uint2& uh, uint2& ul) {
    __half2 h01 = __floats2half2_rn(v.x, v.y);
    __half2 h23 = __floats2half2_rn(v.z, v.w);
    float2 f01 = __half22float2(h01);
    float2 f23 = __half22float2(h23);
    __half2 l01 = __floats2half2_rn(v.x - f01.x, v.y - f01.y);
    __half2 l23 = __floats2half2_rn(v.z - f23.x, v.w - f23.y);
    uh.x = *(uint32_t*)&h01; uh.y = *(uint32_t*)&h23;
    ul.x = *(uint32_t*)&l01; ul.y = *(uint32_t*)&l23;
}
__device__ __forceinline__ void cvt2(float v0, float v1, uint32_t& h, uint32_t& l) {
    __half2 hh = __floats2half2_rn(v0, v1);
    float2 hf = __half22float2(hh);
    __half2 ll = __floats2half2_rn(v0 - hf.x, v1 - hf.y);
    h = *(uint32_t*)&hh; l = *(uint32_t*)&ll;
}

// ---------------- small kernels ----------------
__global__ void cvt_planes(const float* __restrict__ src,
                           __half* __restrict__ dh,
                           __half* __restrict__ dl, int n4) {
    int i = blockIdx.x * 256 + threadIdx.x;
    if (i >= n4) return;
    float4 v = ((const float4*)src)[i];
    uint2 uh, ul;
    cvt4(v, uh, ul);
    ((uint2*)dh)[i] = uh;
    ((uint2*)dl)[i] = ul;
}

__global__ void cvt_hi(const float* __restrict__ src, __half* __restrict__ dh, int n4) {
    int i = blockIdx.x * 256 + threadIdx.x;
    if (i >= n4) return;
    float4 v = ((const float4*)src)[i];
    __half2 h01 = __floats2half2_rn(v.x, v.y);
    __half2 h23 = __floats2half2_rn(v.z, v.w);
    uint2 uh;
    uh.x = *(uint32_t*)&h01; uh.y = *(uint32_t*)&h23;
    ((uint2*)dh)[i] = uh;
}

__global__ void posembed_kernel(const float* __restrict__ x,
                                const int* __restrict__ tokens) {
    int i = blockIdx.x * 256 + threadIdx.x;
    int c4 = (i & 127) * 4;
    int row = i >> 7;
    int t = row >> 1, b = row & 1;
    int tok = tokens[b * T_SEQ + t];
    float4 v = ((const float4*)x)[i];
    if (tok != 0) {
        float p = (float)(t + 1);
        float* pv = (float*)&v;
#pragma unroll
        for (int e = 0; e < 4; e++) {
            int c = c4 + e;
            int ii = (c < 256) ? c : c - 256;
            float ang = p * expf((float)ii * (-9.210340371976184f / 255.0f));
            pv[e] += (c < 256) ? sinf(ang) : cosf(ang);
        }
    }
    ((float4*)g_x)[i] = v;
    uint2 uh, ul;
    cvt4(v, uh, ul);
    ((uint2*)g_xh)[i] = uh;
    ((uint2*)g_xl)[i] = ul;
}

// vsum (exact: hi+lo) + folded min/max init
__global__ void vsum_kernel(int selfmask) {
    const int bh = blockIdx.x;
    if (bh == 0 && threadIdx.x == 0) {
        if (selfmask) { g_minmax[0] = fenc(0.f); g_minmax[1] = fenc(0.f); }
        else          { g_minmax[0] = 0xFFFFFFFFu; g_minmax[1] = 0u; }
    }
    const int b = bh >> 3, h = bh & 7;
    const __half* vh = g_qkvh + b * QKV_LD + 2 * EMBED + h * HD;
    const __half* vl = g_qkvl + b * QKV_LD + 2 * EMBED + h * HD;
    const int d = threadIdx.x & 63;
    const int part = threadIdx.x >> 6;
    float s = 0.f;
    for (int i = part * 512; i < part * 512 + 512; i++) {
        size_t off = (size_t)i * ROWSTRIDE + d;
        s += __half2float(vh[off]) + __half2float(vl[off]);
    }
    __shared__ float sm[256];
    sm[threadIdx.x] = s;
    __syncthreads();
    if (threadIdx.x < 64)
        g_vsum[b * EMBED + h * HD + d] = sm[d] + sm[64 + d] + sm[128 + d] + sm[192 + d];
}

// vs2[b][n] = sum_c vsum[b][c] * Wo[n][c]
__global__ void vs2_kernel(const float* __restrict__ Wo) {
    int idx = blockIdx.x * 256 + threadIdx.x;  // 1024
    int b = idx >> 9, n = idx & 511;
    const float* vs = g_vsum + b * EMBED;
    const float* w = Wo + (size_t)n * EMBED;
    float s = 0.f;
    for (int c = 0; c < EMBED; c += 4) {
        float4 wv = *(const float4*)(w + c);
        s += vs[c] * wv.x + vs[c + 1] * wv.y + vs[c + 2] * wv.z + vs[c + 3] * wv.w;
    }
    g_vs2[idx] = s;
}

// warp-per-row LN
__global__ __launch_bounds__(256)
void ln_kernel(const float* __restrict__ res, const float* __restrict__ y,
               const float* __restrict__ gam, const float* __restrict__ bet,
               float* __restrict__ out,
               __half* __restrict__ outh, __half* __restrict__ outl) {
    const int row = blockIdx.x * 8 + (threadIdx.x >> 5);
    const int lane = threadIdx.x & 31;
    const size_t base = (size_t)row * EMBED;
    float v[16];
    float s = 0.f, q = 0.f;
#pragma unroll
    for (int k = 0; k < 4; k++) {
        const int c = lane * 4 + k * 128;
        float4 a = *(const float4*)(res + base + c);
        float4 bb = *(const float4*)(y + base + c);
        float t0 = a.x + bb.x, t1 = a.y + bb.y, t2 = a.z + bb.z, t3 = a.w + bb.w;
        v[k * 4 + 0] = t0; v[k * 4 + 1] = t1; v[k * 4 + 2] = t2; v[k * 4 + 3] = t3;
        s += t0 + t1 + t2 + t3;
        q += t0 * t0 + t1 * t1 + t2 * t2 + t3 * t3;
    }
#pragma unroll
    for (int off = 16; off > 0; off >>= 1) {
        s += __shfl_xor_sync(0xffffffffu, s, off);
        q += __shfl_xor_sync(0xffffffffu, q, off);
    }
    const float mu = s * (1.f / 512.f);
    const float var = q * (1.f / 512.f) - mu * mu;
    const float rs = rsqrtf(fmaxf(var, 0.f) + 1e-20f);
#pragma unroll
    for (int k = 0; k < 4; k++) {
        const int c = lane * 4 + k * 128;
        float4 g4 = *(const float4*)(gam + c);
        float4 b4 = *(const float4*)(bet + c);
        float4 o;
        o.x = (v[k * 4 + 0] - mu) * rs * g4.x + b4.x;
        o.y = (v[k * 4 + 1] - mu) * rs * g4.y + b4.y;
        o.z = (v[k * 4 + 2] - mu) * rs * g4.z + b4.z;
        o.w = (v[k * 4 + 3] - mu) * rs * g4.w + b4.w;
        *(float4*)(out + base + c) = o;
        uint2 uh, ul;
        cvt4(o, uh, ul);
        *(uint2*)(outh + base + c) = uh;
        *(uint2*)(outl + base + c) = ul;
    }
}

// ---------------- fused attention (3-stage pipeline, 1 sync/iter) ----------------
__global__ __launch_bounds__(256, 1)
void fused_attn(int selfmask) {
    const int bid = blockIdx.x;
    const int bh = bid & 15, b = bh >> 3, h = bh & 7;
    const int tile = bid >> 4;
    const int bt = (selfmask ? (15 - tile) : tile) * 128;
    extern __shared__ char dyn[];
    const uint32_t u0 = smem_u32(dyn);
    const int tid = threadIdx.x, wid = tid >> 5, lane = tid & 31;
    const int trow = wid * 16;
    const __half* qh = g_qkvh + b * QKV_LD + h * HD;
    const __half* ql = g_qkvl + b * QKV_LD + h * HD;
    const __half* kh = g_qkvh + b * QKV_LD + EMBED + h * HD;
    const __half* vh = g_qkvh + b * QKV_LD + 2 * EMBED + h * HD;
    const int nst = selfmask ? (bt / 128 + 1) : 16;

    const int lr = tid >> 3, lc = (tid & 7) * 8;  // base row [0,32), col [0,64)

    // K/V stage loader: 4 rows per thread => full 128 rows (R9 bug: covered 32 only)
    auto issue_kv = [&](int s0, uint32_t base) {
#pragma unroll
        for (int j = 0; j < 4; j++) {
            const int r = lr + 32 * j;
            uint32_t dk = base + (r * SQ + lc) * 2;
            cpa16(dk,         kh + (size_t)(s0 + r) * ROWSTRIDE + lc);
            cpa16(dk + 18432, vh + (size_t)(s0 + r) * ROWSTRIDE + lc);
        }
        CPA_COMMIT();
    };

    // prologue: group0 = Q hi/lo + stage0; group1 = stage1 (if any)
    {
#pragma unroll
        for (int j = 0; j < 4; j++) {
            const int r = lr + 32 * j;
            uint32_t dq = u0 + (r * SQ + lc) * 2;
            cpa16(dq,         qh + (size_t)(bt + r) * ROWSTRIDE + lc);
            cpa16(dq + 18432, ql + (size_t)(bt + r) * ROWSTRIDE + lc);
            uint32_t dk = u0 + FA_QB + (r * SQ + lc) * 2;
            cpa16(dk,         kh + (size_t)r * ROWSTRIDE + lc);
            cpa16(dk + 18432, vh + (size_t)r * ROWSTRIDE + lc);
        }
        CPA_COMMIT();
        if (nst > 1) issue_kv(128, u0 + FA_QB + FA_SSTG);
    }

    uint32_t qfh[4][4], qfl[4][4];
    float oacc[8][4] = {};
    float lmin = 3.4e38f, lmax = -3.4e38f;

    for (int st = 0; st < nst; st++) {
        const uint32_t sb = u0 + FA_QB + (st % 3) * FA_SSTG;
        if (st + 1 < nst) CPA_WAIT1(); else CPA_WAIT0();
        __syncthreads();
        // issue stage st+2 AFTER sync (safe: all warps done with compute st-1)
        if (st + 2 < nst)
            issue_kv((st + 2) * 128, u0 + FA_QB + ((st + 2) % 3) * FA_SSTG);
        if (st == 0) {
#pragma unroll
            for (int ks = 0; ks < 4; ks++) {
                uint32_t off = u0 + ((trow + (lane & 15)) * SQ + ks * 16 + (lane >> 4) * 8) * 2;
                ldmx4(qfh[ks], off);
                ldmx4(qfl[ks], off + 18432);
            }
        }
        // ---- S = Q @ K^T (K hi only) ----
        float sacc[16][4] = {};
#pragma unroll
        for (int ks = 0; ks < 4; ks++) {
#pragma unroll
            for (int j4 = 0; j4 < 8; j4++) {
                uint32_t off = sb + ((j4 * 16 + ((lane >> 4) & 1) * 8 + (lane & 7)) * SQ
                               + ks * 16 + ((lane >> 3) & 1) * 8) * 2;
                uint32_t kbh[4];
                ldmx4(kbh, off);
#pragma unroll
                for (int jj = 0; jj < 2; jj++) {
                    int j = j4 * 2 + jj;
                    mma16816(sacc[j], qfh[ks], &kbh[jj * 2]);
                    mma16816(sacc[j], qfl[ks], &kbh[jj * 2]);
                }
            }
        }
        // ---- scale/mask/minmax + register repack C-frag -> A-frag (hi/lo) ----
        const int diag = selfmask && (st == nst - 1);
        const int tg0 = bt + trow + (lane >> 2);
        const int sg0 = st * 128 + (lane & 3) * 2;
        uint32_t sfh[8][4], sfl[8][4];
#pragma unroll
        for (int j = 0; j < 16; j++) {
            float v0 = sacc[j][0] * 0.125f, v1 = sacc[j][1] * 0.125f;
            float v2 = sacc[j][2] * 0.125f, v3 = sacc[j][3] * 0.125f;
            if (diag) {
                int s = sg0 + j * 8;
                if (s + 0 > tg0) v0 = 0.f;
                if (s + 1 > tg0) v1 = 0.f;
                if (s + 0 > tg0 + 8) v2 = 0.f;
                if (s + 1 > tg0 + 8) v3 = 0.f;
            }
            lmin = fminf(lmin, fminf(fminf(v0, v1), fminf(v2, v3)));
            lmax = fmaxf(lmax, fmaxf(fmaxf(v0, v1), fmaxf(v2, v3)));
            int p = j >> 1, q = (j & 1) * 2;
            cvt2(v0, v1, sfh[p][q], sfl[p][q]);
            cvt2(v2, v3, sfh[p][q + 1], sfl[p][q + 1]);
        }
        // ---- O += S @ V (V hi only, B-frag via ldmatrix.trans) ----
        const uint32_t vb = sb + FA_VOFF;
#pragma unroll
        for (int p = 0; p < 8; p++) {
#pragma unroll
            for (int jd4 = 0; jd4 < 4; jd4++) {
                uint32_t off = vb + ((p * 16 + (lane & 15)) * SQ + jd4 * 16 + (lane >> 4) * 8) * 2;
                uint32_t vbh[4];
                ldmx4t(vbh, off);
#pragma unroll
                for (int jj = 0; jj < 2; jj++) {
                    int jd = jd4 * 2 + jj;
                    mma16816(oacc[jd], sfh[p], &vbh[jj * 2]);
                    mma16816(oacc[jd], sfl[p], &vbh[jj * 2]);
                }
            }
        }
    }

    // ---- epilogue: write O_raw fp16 planes ----
    const int r = lane >> 2, tig = lane & 3;
#pragma unroll
    for (int jd = 0; jd < 8; jd++) {
        const int d = jd * 8 + tig * 2;
#pragma unroll
        for (int half = 0; half < 2; half++) {
            const int t = bt + trow + r + half * 8;
            uint32_t hw, lw;
            cvt2(oacc[jd][half * 2], oacc[jd][half * 2 + 1], hw, lw);
            size_t off = (size_t)(t * BATCH + b) * EMBED + h * HD + d;
            *(uint32_t*)(g_ah + off) = hw;
            *(uint32_t*)(g_al + off) = lw;
        }
    }
    // ---- global min/max ----
#pragma unroll
    for (int off = 16; off > 0; off >>= 1) {
        lmin = fminf(lmin, __shfl_xor_sync(0xffffffffu, lmin, off));
        lmax = fmaxf(lmax, __shfl_xor_sync(0xffffffffu, lmax, off));
    }
    __shared__ float rmn[8], rmx[8];
    if (lane == 0) { rmn[wid] = lmin; rmx[wid] = lmax; }
    __syncthreads();
    if (tid == 0) {
        float mn = rmn[0], mx = rmx[0];
#pragma unroll
        for (int w = 1; w < 8; w++) { mn = fminf(mn, rmn[w]); mx = fmaxf(mx, rmx[w]); }
        atomicMin(&g_minmax[0], fenc(mn));
        atomicMax(&g_minmax[1], fenc(mx));
    }
}

// ---------------- mma linear (3-stage pipeline, 1 sync/iter) ----------------
// mode 0: fp32 out; 1: fp16 planes out; 2: planes + relu; 3: fp32 + deferred norm
#define LIN_STG 30720
__global__ __launch_bounds__(256)
void mma_linear(const __half* __restrict__ Aqh, const __half* __restrict__ Aql,
                const __half* __restrict__ Akvh, const __half* __restrict__ Akvl,
                int nsplit,
                const __half* __restrict__ Bh,
                const float* __restrict__ bias, int N, int K, int mode,
                const float* __restrict__ vs2,
                float* __restrict__ Cf, __half* __restrict__ Ch,
                __half* __restrict__ Cl) {
    extern __shared__ char dyn[];
    const uint32_t u0 = smem_u32(dyn);
    const int tid = threadIdx.x, wid = tid >> 5, lane = tid & 31;
    const int bn = blockIdx.x * 128, bm = blockIdx.y * 128;
    const __half* Ah = (bn < nsplit) ? Aqh : Akvh;
    const __half* Al = (bn < nsplit) ? Aql : Akvl;
    const int wm = (wid >> 2) * 64, wn = (wid & 3) * 32;

    float acc[4][4][4] = {};
    const int nkt = K >> 5;
    const int lr2 = tid >> 1, lc2 = (tid & 1) * 8;

    // per stage: A-hi [0,10240), A-lo [10240,20480), B-hi [20480,30720)
    auto issue_stage = [&](int kt, uint32_t base) {
        const int kc = kt * 32;
#pragma unroll
        for (int half = 0; half < 2; half++) {
            int r = lr2, c = lc2 + half * 16;
            uint32_t d = base + (r * S32 + c) * 2;
            cpa16(d,         Ah + (size_t)(bm + r) * K + kc + c);
            cpa16(d + 10240, Al + (size_t)(bm + r) * K + kc + c);
            cpa16(d + 20480, Bh + (size_t)(bn + r) * K + kc + c);
        }
        CPA_COMMIT();
    };

    issue_stage(0, u0);
    issue_stage(1, u0 + LIN_STG);

    for (int kt = 0; kt < nkt; kt++) {
        const uint32_t sb = u0 + (kt % 3) * LIN_STG;
        if (kt + 1 < nkt) CPA_WAIT1(); else CPA_WAIT0();
        __syncthreads();
        if (kt + 2 < nkt) issue_stage(kt + 2, u0 + ((kt + 2) % 3) * LIN_STG);
#pragma unroll
        for (int ks = 0; ks < 2; ks++) {
            uint32_t ah[4][4], al[4][4], bh[2][4];
#pragma unroll
            for (int i = 0; i < 4; i++) {
                uint32_t off = sb + ((wm + i * 16 + (lane & 15)) * S32 + ks * 16 + (lane >> 4) * 8) * 2;
                ldmx4(ah[i], off);
                ldmx4(al[i], off + 10240);
            }
#pragma unroll
            for (int j2 = 0; j2 < 2; j2++) {
                uint32_t off = sb + ((wn + j2 * 16 + ((lane >> 4) & 1) * 8 + (lane & 7)) * S32
                               + ks * 16 + ((lane >> 3) & 1) * 8) * 2;
                ldmx4(bh[j2], off + 20480);
            }
#pragma unroll
            for (int i = 0; i < 4; i++)
#pragma unroll
                for (int j = 0; j < 4; j++) {
                    const uint32_t* bhf = &bh[j >> 1][(j & 1) * 2];
                    mma16816(acc[i][j], ah[i], bhf);
                    mma16816(acc[i][j], al[i], bhf);
                }
        }
    }
    float mn = 0.f, inv = 1.f;
    if (mode == 3) {
        mn = fdec(g_minmax[0]);
        inv = 1.f / (fdec(g_minmax[1]) - mn);
    }
#pragma unroll
    for (int i = 0; i < 4; i++) {
        const int m0 = bm + wm + i * 16 + (lane >> 2);
#pragma unroll
        for (int j = 0; j < 4; j++) {
            const int n0 = bn + wn + j * 8 + (lane & 3) * 2;
            float b0 = bias[n0], b1 = bias[n0 + 1];
#pragma unroll
            for (int half = 0; half < 2; half++) {
                const int m = m0 + half * 8;
                float v0 = acc[i][j][half * 2 + 0];
                float v1 = acc[i][j][half * 2 + 1];
                if (mode == 3) {
                    const int bb = m & 1;
                    v0 = (v0 - mn * vs2[bb * EMBED + n0]) * inv + b0;
                    v1 = (v1 - mn * vs2[bb * EMBED + n0 + 1]) * inv + b1;
                    float2 o = make_float2(v0, v1);
                    *(float2*)(Cf + (size_t)m * N + n0) = o;
                } else {
                    v0 += b0; v1 += b1;
                    if (mode == 2) { v0 = fmaxf(v0, 0.f); v1 = fmaxf(v1, 0.f); }
                    if (mode == 0) {
                        float2 o = make_float2(v0, v1);
                        *(float2*)(Cf + (size_t)m * N + n0) = o;
                    } else {
                        uint32_t hh, ll;
                        cvt2(v0, v1, hh, ll);
                        *(uint32_t*)(Ch + (size_t)m * N + n0) = hh;
                        *(uint32_t*)(Cl + (size_t)m * N + n0) = ll;
                    }
                }
            }
        }
    }
}

// ---------------- host orchestration ----------------
extern "C" void kernel_launch(void* const* d_in, const int* in_sizes, int n_in,
                              void* d_out, int out_size) {
    const float* x         = (const float*)d_in[0];
    const float* enc_out   = (const float*)d_in[1];
    const int*   tokens    = (const int*)d_in[2];
    const float* self_Wqkv = (const float*)d_in[3];
    const float* self_bqkv = (const float*)d_in[4];
    const float* self_Wo   = (const float*)d_in[5];
    const float* self_bo   = (const float*)d_in[6];
    const float* cross_Wqkv= (const float*)d_in[7];
    const float* cross_bqkv= (const float*)d_in[8];
    const float* cross_Wo  = (const float*)d_in[9];
    const float* cross_bo  = (const float*)d_in[10];
    const float* fc1_w     = (const float*)d_in[11];
    const float* fc1_b     = (const float*)d_in[12];
    const float* fc2_w     = (const float*)d_in[13];
    const float* fc2_b     = (const float*)d_in[14];
    const float* ln1_g     = (const float*)d_in[15];
    const float* ln1_b     = (const float*)d_in[16];
    const float* ln2_g     = (const float*)d_in[17];
    const float* ln2_b     = (const float*)d_in[18];
    const float* ln3_g     = (const float*)d_in[19];
    const float* ln3_b     = (const float*)d_in[20];

    float *px, *py, *pvs2;
    __half *pxh, *pxl, *pench, *pencl, *pqkvh, *pqkvl, *phidh, *phidl, *pah, *pal, *pwbh;
    cudaGetSymbolAddress((void**)&px, g_x);
    cudaGetSymbolAddress((void**)&py, g_y);
    cudaGetSymbolAddress((void**)&pvs2, g_vs2);
    cudaGetSymbolAddress((void**)&pxh, g_xh);
    cudaGetSymbolAddress((void**)&pxl, g_xl);
    cudaGetSymbolAddress((void**)&pench, g_ench);
    cudaGetSymbolAddress((void**)&pencl, g_encl);
    cudaGetSymbolAddress((void**)&pqkvh, g_qkvh);
    cudaGetSymbolAddress((void**)&pqkvl, g_qkvl);
    cudaGetSymbolAddress((void**)&phidh, g_hidh);
    cudaGetSymbolAddress((void**)&phidl, g_hidl);
    cudaGetSymbolAddress((void**)&pah, g_ah);
    cudaGetSymbolAddress((void**)&pal, g_al);
    cudaGetSymbolAddress((void**)&pwbh, g_wbh);

    const int SM_LIN = 3 * LIN_STG;  // 92160
    cudaFuncSetAttribute(mma_linear, cudaFuncAttributeMaxDynamicSharedMemorySize, SM_LIN);
    cudaFuncSetAttribute(fused_attn, cudaFuncAttributeMaxDynamicSharedMemorySize, FA_SMEM);

    auto cvtw = [&](const float* src, size_t off, int n) {
        cvt_hi<<<(n / 4 + 255) / 256, 256>>>(src, pwbh + off, n / 4);
    };
    cvtw(self_Wqkv, S_SQKV, 4 * QKV_LD * EMBED);
    cvtw(self_Wo,   S_SWO,  4 * EMBED * EMBED);
    cvtw(cross_Wqkv,S_CQKV, 4 * QKV_LD * EMBED);
    cvtw(cross_Wo,  S_CWO,  4 * EMBED * EMBED);
    cvtw(fc1_w,     S_FC1,  4 * FFN_DIM * EMBED);
    cvtw(fc2_w,     S_FC2,  4 * EMBED * FFN_DIM);
    cvt_planes<<<(NROWS * EMBED / 4 + 255) / 256, 256>>>(enc_out, pench, pencl, NROWS * EMBED / 4);

    posembed_kernel<<<NROWS * EMBED / 4 / 256, 256>>>(x, tokens);

    const int BIG = 1 << 30;
    for (int l = 0; l < 4; l++) {
        // ---- self attention ----
        mma_linear<<<dim3(12, 32), 256, SM_LIN>>>(pxh, pxl, pxh, pxl, BIG,
            pwbh + S_SQKV + (size_t)l * QKV_LD * EMBED,
            self_bqkv + l * QKV_LD, QKV_LD, EMBED, 1, nullptr, nullptr, pqkvh, pqkvl);
        vsum_kernel<<<16, 256>>>(1);
        fused_attn<<<256, 256, FA_SMEM>>>(1);
        vs2_kernel<<<4, 256>>>(self_Wo + (size_t)l * EMBED * EMBED);
        mma_linear<<<dim3(4, 32), 256, SM_LIN>>>(pah, pal, pah, pal, BIG,
            pwbh + S_SWO + (size_t)l * EMBED * EMBED,
            self_bo + l * EMBED, EMBED, EMBED, 3, pvs2, py, nullptr, nullptr);
        ln_kernel<<<NROWS / 8, 256>>>(px, py, ln1_g + l * EMBED, ln1_b + l * EMBED, px, pxh, pxl);

        // ---- cross attention ----
        mma_linear<<<dim3(12, 32), 256, SM_LIN>>>(pxh, pxl, pench, pencl, EMBED,
            pwbh + S_CQKV + (size_t)l * QKV_LD * EMBED,
            cross_bqkv + l * QKV_LD, QKV_LD, EMBED, 1, nullptr, nullptr, pqkvh, pqkvl);
        vsum_kernel<<<16, 256>>>(0);
        fused_attn<<<256, 256, FA_SMEM>>>(0);
        vs2_kernel<<<4, 256>>>(cross_Wo + (size_t)l * EMBED * EMBED);
        mma_linear<<<dim3(4, 32), 256, SM_LIN>>>(pah, pal, pah, pal, BIG,
            pwbh + S_CWO + (size_t)l * EMBED * EMBED,
            cross_bo + l * EMBED, EMBED, EMBED, 3, pvs2, py, nullptr, nullptr);
        ln_kernel<<<NROWS / 8, 256>>>(px, py, ln2_g + l * EMBED, ln2_b + l * EMBED, px, pxh, pxl);

        // ---- FFN ----
        mma_linear<<<dim3(16, 32), 256, SM_LIN>>>(pxh, pxl, pxh, pxl, BIG,
            pwbh + S_FC1 + (size_t)l * FFN_DIM * EMBED,
            fc1_b + l * FFN_DIM, FFN_DIM, EMBED, 2, nullptr, nullptr, phidh, phidl);
        mma_linear<<<dim3(4, 32), 256, SM_LIN>>>(phidh, phidl, phidh, phidl, BIG,
            pwbh + S_FC2 + (size_t)l * EMBED * FFN_DIM,
            fc2_b + l * EMBED, EMBED, FFN_DIM, 0, nullptr, py, nullptr, nullptr);
        float* lnout = (l == 3) ? (float*)d_out : px;
        ln_kernel<<<NROWS / 8, 256>>>(px, py, ln3_g + l * EMBED, ln3_b + l * EMBED, lnout, pxh, pxl);
    }
}